// round 11
// baseline (speedup 1.0000x reference)
#include <cuda_runtime.h>
#include <cuda_fp16.h>

// ---------------- problem constants ----------------
#define NMAX 100000
#define EMAX 1600000
#define INF 512
#define D1 64      // H1*F1 = 8*8
#define H1N 8
#define D2 40      // H2*F2 = 1*40

// ---------------- device scratch ----------------
__device__ __align__(16) __half g_h1h [NMAX * D1];   // fp16 layer1 features (gather payload)
__device__ __align__(16) __half g_el1h[NMAX * H1N];  // fp16 src-side attention
__device__ __align__(16) float  g_er1 [NMAX * H1N];  // fp32 dst-side attention
__device__ __align__(16) float  g_agg1[NMAX * D1];   // normalized layer1 output (pre-bias)
__device__ __align__(16) __half g_h2h [NMAX * D2];   // fp16 layer2 features
__device__ __align__(16) __half g_el2h[NMAX];
__device__ __align__(16) float  g_er2 [NMAX];
// CSR scratch
__device__ int g_hist[NMAX];
__device__ int g_rowstart[NMAX];
__device__ int g_cursor[NMAX];
__device__ int g_sorted[EMAX];
__device__ int g_counter;

// ---------------- helpers ----------------
__device__ __forceinline__ float lrelu(float v) { return v >= 0.f ? v : 0.2f * v; }
__device__ __forceinline__ float eluf(float v)  { return v > 0.f ? v : expm1f(v); }

__device__ __forceinline__ unsigned tf32c(float f) {
    unsigned u;
    asm("cvt.rna.tf32.f32 %0, %1;" : "=r"(u) : "f"(f));
    return u;
}
__device__ __forceinline__ void mma_tf32(float* c,
                                         unsigned a0, unsigned a1, unsigned a2, unsigned a3,
                                         unsigned b0, unsigned b1) {
    asm volatile(
        "mma.sync.aligned.m16n8k8.row.col.f32.tf32.tf32.f32 "
        "{%0,%1,%2,%3},{%4,%5,%6,%7},{%8,%9},{%0,%1,%2,%3};"
        : "+f"(c[0]), "+f"(c[1]), "+f"(c[2]), "+f"(c[3])
        : "r"(a0), "r"(a1), "r"(a2), "r"(a3), "r"(b0), "r"(b1));
}

// ---------------- K0: zero hist + counter ----------------
__global__ void k_zero(int n) {
    int i = blockIdx.x * 256 + threadIdx.x;
    if (i < n) g_hist[i] = 0;
    if (i == 0) g_counter = 0;
}

// ---------------- K_hist ----------------
__global__ __launch_bounds__(256) void k_hist(const int* __restrict__ dst, int e) {
    int i = blockIdx.x * 256 + threadIdx.x;
    if (i < e) atomicAdd(&g_hist[dst[i]], 1);
}

// ---------------- K_rowalloc: warp-scanned row offsets ----------------
__global__ __launch_bounds__(256) void k_rowalloc(int n) {
    int d = blockIdx.x * 256 + threadIdx.x;
    int lane = threadIdx.x & 31;
    int c = (d < n) ? g_hist[d] : 0;
    int sum = c;
#pragma unroll
    for (int off = 1; off < 32; off <<= 1) {
        int v = __shfl_up_sync(0xffffffffu, sum, off);
        if (lane >= off) sum += v;
    }
    int total = __shfl_sync(0xffffffffu, sum, 31);
    int base = 0;
    if (lane == 31) base = atomicAdd(&g_counter, total);
    base = __shfl_sync(0xffffffffu, base, 31);
    if (d < n) {
        int st = base + sum - c;
        g_rowstart[d] = st;
        g_cursor[d]   = st;
    }
}

// ---------------- K_scatter ----------------
__global__ __launch_bounds__(256) void k_scatter(const int* __restrict__ src,
                                                 const int* __restrict__ dst, int e) {
    int i = blockIdx.x * 256 + threadIdx.x;
    if (i >= e) return;
    int p = atomicAdd(&g_cursor[dst[i]], 1);
    g_sorted[p] = src[i];
}

// ---------------- K1: h1 = x @ W1 via tf32 mma.sync; fused el1/er1 + fp16 store ----------------
__global__ __launch_bounds__(256) void k_gemm1(const float* __restrict__ x,
                                               const float* __restrict__ W1,
                                               const float* __restrict__ al1,
                                               const float* __restrict__ ar1, int n) {
    __shared__ __align__(16) float sm[8320];   // xs(4608) + ws(2048) | ds(8192), al/ar at 8192
    unsigned* xsu = (unsigned*)sm;
    unsigned* wsu = (unsigned*)(sm + 4608);

    const int tx = threadIdx.x;
    const int row0 = blockIdx.x * 128;
    const int warp = tx >> 5;
    const int lane = tx & 31;
    const int g  = lane >> 2;
    const int tg = lane & 3;
    const int wrow = warp * 16;

    if (tx < 64) sm[8192 + tx] = al1[tx];
    else if (tx < 128) sm[8192 + tx] = ar1[tx - 64];

    float4 xr[4];
    float4 wr[2];

#pragma unroll
    for (int it = 0; it < 4; it++) {
        int slot = tx + it * 256;
        int r = slot >> 3;
        int kk = (slot & 7) << 2;
        int grow = row0 + r;
        xr[it] = (grow < n) ? *(const float4*)(x + (size_t)grow * INF + kk)
                            : make_float4(0.f, 0.f, 0.f, 0.f);
    }
#pragma unroll
    for (int it = 0; it < 2; it++) {
        int slot = tx + it * 256;
        int k = slot >> 4;
        int n4 = (slot & 15) << 2;
        wr[it] = *(const float4*)(W1 + (size_t)k * D1 + n4);
    }
#pragma unroll
    for (int it = 0; it < 4; it++) {
        int slot = tx + it * 256;
        int r = slot >> 3;
        int kk = (slot & 7) << 2;
        *(uint4*)&xsu[r * 36 + kk] =
            make_uint4(tf32c(xr[it].x), tf32c(xr[it].y), tf32c(xr[it].z), tf32c(xr[it].w));
    }
#pragma unroll
    for (int it = 0; it < 2; it++) {
        int slot = tx + it * 256;
        int k = slot >> 4;
        int n4 = (slot & 15) << 2;
        int base = (k >> 2) * 256 + (k & 3);
        wsu[base + (n4 + 0) * 4] = tf32c(wr[it].x);
        wsu[base + (n4 + 1) * 4] = tf32c(wr[it].y);
        wsu[base + (n4 + 2) * 4] = tf32c(wr[it].z);
        wsu[base + (n4 + 3) * 4] = tf32c(wr[it].w);
    }
    __syncthreads();

    float acc[8][4];
#pragma unroll
    for (int j = 0; j < 8; j++)
#pragma unroll
        for (int q = 0; q < 4; q++) acc[j][q] = 0.f;

    for (int tt = 0; tt < 16; tt++) {
        if (tt < 15) {
            int k0 = (tt + 1) * 32;
#pragma unroll
            for (int it = 0; it < 4; it++) {
                int slot = tx + it * 256;
                int r = slot >> 3;
                int kk = (slot & 7) << 2;
                int grow = row0 + r;
                xr[it] = (grow < n) ? *(const float4*)(x + (size_t)grow * INF + k0 + kk)
                                    : make_float4(0.f, 0.f, 0.f, 0.f);
            }
#pragma unroll
            for (int it = 0; it < 2; it++) {
                int slot = tx + it * 256;
                int k = slot >> 4;
                int n4 = (slot & 15) << 2;
                wr[it] = *(const float4*)(W1 + (size_t)(k0 + k) * D1 + n4);
            }
        }

#pragma unroll
        for (int k8 = 0; k8 < 4; k8++) {
            int kb = k8 * 8;
            unsigned a0 = xsu[(wrow + g) * 36 + kb + tg];
            unsigned a1 = xsu[(wrow + g + 8) * 36 + kb + tg];
            unsigned a2 = xsu[(wrow + g) * 36 + kb + tg + 4];
            unsigned a3 = xsu[(wrow + g + 8) * 36 + kb + tg + 4];
            const unsigned* wp = wsu + k8 * 512 + 4 * g + tg;
#pragma unroll
            for (int j = 0; j < 8; j++) {
                unsigned b0 = wp[32 * j];
                unsigned b1 = wp[256 + 32 * j];
                mma_tf32(acc[j], a0, a1, a2, a3, b0, b1);
            }
        }
        __syncthreads();
        if (tt < 15) {
#pragma unroll
            for (int it = 0; it < 4; it++) {
                int slot = tx + it * 256;
                int r = slot >> 3;
                int kk = (slot & 7) << 2;
                *(uint4*)&xsu[r * 36 + kk] =
                    make_uint4(tf32c(xr[it].x), tf32c(xr[it].y), tf32c(xr[it].z), tf32c(xr[it].w));
            }
#pragma unroll
            for (int it = 0; it < 2; it++) {
                int slot = tx + it * 256;
                int k = slot >> 4;
                int n4 = (slot & 15) << 2;
                int base = (k >> 2) * 256 + (k & 3);
                wsu[base + (n4 + 0) * 4] = tf32c(wr[it].x);
                wsu[base + (n4 + 1) * 4] = tf32c(wr[it].y);
                wsu[base + (n4 + 2) * 4] = tf32c(wr[it].z);
                wsu[base + (n4 + 3) * 4] = tf32c(wr[it].w);
            }
            __syncthreads();
        }
    }

    float* ds = sm;
#pragma unroll
    for (int j = 0; j < 8; j++) {
        *(float2*)&ds[(wrow + g) * 64 + 8 * j + 2 * tg]     = make_float2(acc[j][0], acc[j][1]);
        *(float2*)&ds[(wrow + g + 8) * 64 + 8 * j + 2 * tg] = make_float2(acc[j][2], acc[j][3]);
    }
    __syncthreads();

    {
        int row = tx >> 1;
        int ch = tx & 1;
        int grow = row0 + row;
        if (grow < n) {
            const float* dp  = ds + row * 64 + ch * 32;
            const float* alp = sm + 8192 + ch * 32;
            const float* arp = sm + 8256 + ch * 32;
            float h[32];
#pragma unroll
            for (int q = 0; q < 8; q++) *(float4*)&h[q * 4] = *(const float4*)(dp + q * 4);

            float elv[4], erv[4];
#pragma unroll
            for (int q = 0; q < 4; q++) {
                float el = 0.f, er = 0.f;
#pragma unroll
                for (int c = 0; c < 8; c++) {
                    el = fmaf(h[q * 8 + c], alp[q * 8 + c], el);
                    er = fmaf(h[q * 8 + c], arp[q * 8 + c], er);
                }
                elv[q] = el; erv[q] = er;
            }
            __half2 ph[16];
#pragma unroll
            for (int q = 0; q < 16; q++) ph[q] = __floats2half2_rn(h[2 * q], h[2 * q + 1]);
            uint4* hop = (uint4*)(g_h1h + (size_t)grow * D1 + ch * 32);
#pragma unroll
            for (int q = 0; q < 4; q++) hop[q] = ((uint4*)ph)[q];

            __half e4[4];
#pragma unroll
            for (int q = 0; q < 4; q++) e4[q] = __float2half(elv[q]);
            *(uint2*)(g_el1h + (size_t)grow * 8 + ch * 4) = *(uint2*)e4;
            *(float4*)(g_er1 + (size_t)grow * 8 + ch * 4) =
                make_float4(erv[0], erv[1], erv[2], erv[3]);
        }
    }
}

// ---------------- K3: layer1 CSR aggregation (warp per dst, 8 slots x 4 edge groups) ----------------
__global__ __launch_bounds__(256) void k_agg1(int n) {
    int d = blockIdx.x * 8 + (threadIdx.x >> 5);
    if (d >= n) return;
    int lane = threadIdx.x & 31;
    int j = lane & 7;        // slot / head 0..7
    int g = lane >> 3;       // edge group 0..3

    float er = g_er1[(size_t)d * 8 + j];
    int k0 = g_rowstart[d], k1 = g_cursor[d];

    float acc[8] = {0.f, 0.f, 0.f, 0.f, 0.f, 0.f, 0.f, 0.f};
    float denom = 0.f;
    for (int k = k0 + g; k < k1; k += 4) {
        int s = __ldg(g_sorted + k);
        float el = __half2float(__ldg(g_el1h + (size_t)s * 8 + j));
        uint4 hv = __ldg((const uint4*)(g_h1h + (size_t)s * D1 + j * 8));
        float ex = __expf(lrelu(el + er));
        const __half2* hp = (const __half2*)&hv;
#pragma unroll
        for (int q = 0; q < 4; q++) {
            float2 f = __half22float2(hp[q]);
            acc[2*q]   = fmaf(ex, f.x, acc[2*q]);
            acc[2*q+1] = fmaf(ex, f.y, acc[2*q+1]);
        }
        denom += ex;
    }
    __syncwarp();
    // reduce across the 4 edge groups (lanes j, j+8, j+16, j+24)
#pragma unroll
    for (int q = 0; q < 8; q++) {
        acc[q] += __shfl_down_sync(0xffffffffu, acc[q], 16);
        acc[q] += __shfl_down_sync(0xffffffffu, acc[q], 8);
    }
    denom += __shfl_down_sync(0xffffffffu, denom, 16);
    denom += __shfl_down_sync(0xffffffffu, denom, 8);

    if (g == 0) {
        float iv = denom > 0.f ? __fdividef(1.f, denom) : 0.f;
        float* op = g_agg1 + (size_t)d * D1 + j * 8;
        *(float4*)(op)     = make_float4(acc[0]*iv, acc[1]*iv, acc[2]*iv, acc[3]*iv);
        *(float4*)(op + 4) = make_float4(acc[4]*iv, acc[5]*iv, acc[6]*iv, acc[7]*iv);
    }
}

// ---------------- K4: node: ELU(agg1 + b1), GEMM2 (64->40) vectorized, el2/er2, fp16 h2 ----------------
__global__ __launch_bounds__(256) void k_node2(const float* __restrict__ W2,
                                               const float* __restrict__ al2,
                                               const float* __restrict__ ar2,
                                               const float* __restrict__ b1, int n) {
    __shared__ __align__(16) float w2s[64 * 40];
    __shared__ float sal[40], sar[40], sb1[64];
    for (int i = threadIdx.x; i < 64 * 40; i += 256) w2s[i] = W2[i];
    if (threadIdx.x < 40) { sal[threadIdx.x] = al2[threadIdx.x]; sar[threadIdx.x] = ar2[threadIdx.x]; }
    if (threadIdx.x < 64) sb1[threadIdx.x] = b1[threadIdx.x];
    __syncthreads();
    int nid = blockIdx.x * 256 + threadIdx.x;
    if (nid >= n) return;

    float acc[40];
#pragma unroll
    for (int c = 0; c < 40; c++) acc[c] = 0.f;

    const float4* ap = (const float4*)(g_agg1 + (size_t)nid * D1);
    for (int j = 0; j < 16; j++) {
        float4 tv = ap[j];
        const float* bp = sb1 + j * 4;
        float v0 = eluf(tv.x + bp[0]);
        float v1 = eluf(tv.y + bp[1]);
        float v2 = eluf(tv.z + bp[2]);
        float v3 = eluf(tv.w + bp[3]);
        const float4* w0 = (const float4*)&w2s[(j * 4 + 0) * 40];
        const float4* w1 = (const float4*)&w2s[(j * 4 + 1) * 40];
        const float4* w2 = (const float4*)&w2s[(j * 4 + 2) * 40];
        const float4* w3 = (const float4*)&w2s[(j * 4 + 3) * 40];
#pragma unroll
        for (int q = 0; q < 10; q++) {
            float4 a = w0[q], b = w1[q], c = w2[q], d = w3[q];
            acc[q*4+0] = fmaf(v0, a.x, fmaf(v1, b.x, fmaf(v2, c.x, fmaf(v3, d.x, acc[q*4+0]))));
            acc[q*4+1] = fmaf(v0, a.y, fmaf(v1, b.y, fmaf(v2, c.y, fmaf(v3, d.y, acc[q*4+1]))));
            acc[q*4+2] = fmaf(v0, a.z, fmaf(v1, b.z, fmaf(v2, c.z, fmaf(v3, d.z, acc[q*4+2]))));
            acc[q*4+3] = fmaf(v0, a.w, fmaf(v1, b.w, fmaf(v2, c.w, fmaf(v3, d.w, acc[q*4+3]))));
        }
    }

    float ela = 0.f, era = 0.f;
#pragma unroll
    for (int c = 0; c < 40; c++) {
        ela = fmaf(acc[c], sal[c], ela);
        era = fmaf(acc[c], sar[c], era);
    }
    __half2 hp[20];
#pragma unroll
    for (int q = 0; q < 20; q++) hp[q] = __floats2half2_rn(acc[2*q], acc[2*q+1]);
    uint4* op = (uint4*)(g_h2h + (size_t)nid * D2);
#pragma unroll
    for (int q = 0; q < 5; q++) op[q] = ((uint4*)hp)[q];
    g_el2h[nid] = __float2half(ela);
    g_er2 [nid] = era;
}

// ---------------- K5: layer2 CSR agg + fused bias + log_softmax (warp per dst) ----------------
// lanes 0..29: slot j = lane%10 (4 outputs each), group g = lane/10 walks every 3rd edge.
__global__ __launch_bounds__(256) void k_agg2(const float* __restrict__ b2,
                                              float* __restrict__ out, int n) {
    int d = blockIdx.x * 8 + (threadIdx.x >> 5);
    if (d >= n) return;
    int lane = threadIdx.x & 31;
    int j = lane % 10;
    int g = lane / 10;       // 0,1,2 (lanes 30,31: g==3 -> idle)

    float er = g_er2[d];
    int k0 = g_rowstart[d], k1 = g_cursor[d];
    if (g >= 3) { k0 = 0; k1 = 0; }    // lanes 30,31 skip the loop but join shuffles

    float acc[4] = {0.f, 0.f, 0.f, 0.f};
    float denom = 0.f;
    for (int k = k0 + g; k < k1; k += 3) {
        int s = __ldg(g_sorted + k);
        float el = __half2float(__ldg(g_el2h + s));
        uint2 hv = __ldg((const uint2*)(g_h2h + (size_t)s * D2 + j * 4));
        float ex = __expf(lrelu(el + er));
        const __half2* hp = (const __half2*)&hv;
        float2 f0 = __half22float2(hp[0]);
        float2 f1 = __half22float2(hp[1]);
        acc[0] = fmaf(ex, f0.x, acc[0]);
        acc[1] = fmaf(ex, f0.y, acc[1]);
        acc[2] = fmaf(ex, f1.x, acc[2]);
        acc[3] = fmaf(ex, f1.y, acc[3]);
        denom += ex;
    }
    __syncwarp();
    // fold groups 1,2 into group 0 (lanes j, j+10, j+20)
#pragma unroll
    for (int q = 0; q < 4; q++) {
        float a = __shfl_down_sync(0xffffffffu, acc[q], 10);
        float b = __shfl_down_sync(0xffffffffu, acc[q], 20);
        acc[q] += a + b;
    }
    {
        float a = __shfl_down_sync(0xffffffffu, denom, 10);
        float b = __shfl_down_sync(0xffffffffu, denom, 20);
        denom += a + b;
    }

    // lanes 0..9 now hold the full 40-dim row; fuse bias + log_softmax
    float v[4];
    float m = -1e30f;
    float iv = denom > 0.f ? __fdividef(1.f, denom) : 0.f;
    if (lane < 10) {
#pragma unroll
        for (int q = 0; q < 4; q++) {
            v[q] = acc[q] * iv + __ldg(b2 + j * 4 + q);
            m = fmaxf(m, v[q]);
        }
    }
    // butterfly max over 16-lane subgroup (lanes 10..15 hold -inf)
#pragma unroll
    for (int off = 1; off < 16; off <<= 1)
        m = fmaxf(m, __shfl_xor_sync(0xffffffffu, m, off));
    float s = 0.f;
    if (lane < 10) {
#pragma unroll
        for (int q = 0; q < 4; q++) s += __expf(v[q] - m);
    }
#pragma unroll
    for (int off = 1; off < 16; off <<= 1)
        s += __shfl_xor_sync(0xffffffffu, s, off);

    if (lane < 10) {
        float lse = m + logf(s);
        *(float4*)(out + (size_t)d * D2 + j * 4) =
            make_float4(v[0] - lse, v[1] - lse, v[2] - lse, v[3] - lse);
    }
}

// ---------------- launch ----------------
extern "C" void kernel_launch(void* const* d_in, const int* in_sizes, int n_in,
                              void* d_out, int out_size) {
    const float* x   = (const float*)d_in[0];
    const int*   src = (const int*)d_in[1];
    const int*   dst = (const int*)d_in[2];
    const float* W1  = (const float*)d_in[3];
    const float* al1 = (const float*)d_in[4];
    const float* ar1 = (const float*)d_in[5];
    const float* b1  = (const float*)d_in[6];
    const float* W2  = (const float*)d_in[7];
    const float* al2 = (const float*)d_in[8];
    const float* ar2 = (const float*)d_in[9];
    const float* b2  = (const float*)d_in[10];

    int n = in_sizes[0] / INF;
    int e = in_sizes[1];

    int nb_node = (n + 255) / 256;
    int nb_edge = (e + 255) / 256;
    int nb_gemm = (n + 127) / 128;
    int nb_warp = (n + 7) / 8;          // warp-per-dst kernels

    static cudaStream_t s_side = nullptr;
    static cudaEvent_t  s_evA  = nullptr;
    static cudaEvent_t  s_evB  = nullptr;
    if (s_side == nullptr) {
        cudaStreamCreateWithFlags(&s_side, cudaStreamNonBlocking);
        cudaEventCreateWithFlags(&s_evA, cudaEventDisableTiming);
        cudaEventCreateWithFlags(&s_evB, cudaEventDisableTiming);
    }

    // fork: CSR build on side stream, GEMM1 on main stream
    cudaEventRecord(s_evA, 0);
    cudaStreamWaitEvent(s_side, s_evA, 0);

    k_zero    <<<nb_node, 256, 0, s_side>>>(n);
    k_hist    <<<nb_edge, 256, 0, s_side>>>(dst, e);
    k_rowalloc<<<nb_node, 256, 0, s_side>>>(n);
    k_scatter <<<nb_edge, 256, 0, s_side>>>(src, dst, e);
    cudaEventRecord(s_evB, s_side);

    k_gemm1   <<<nb_gemm, 256>>>(x, W1, al1, ar1, n);

    // join
    cudaStreamWaitEvent(0, s_evB, 0);

    k_agg1    <<<nb_warp, 256>>>(n);
    k_node2   <<<nb_node, 256>>>(W2, al2, ar2, b1, n);
    k_agg2    <<<nb_warp, 256>>>(b2, (float*)d_out, n);
}